// round 7
// baseline (speedup 1.0000x reference)
#include <cuda_runtime.h>
#include <math.h>

#define T_SEQ 2048
#define BATCH 256
// Kernel B per k-quarter (32 k): RKQ in registers (float4-aligned), SKQ in smem
#define RKQ 20
#define SKQ 12

typedef unsigned long long u64;

// xg scratch: [B][T][4H] fp32 = 1 GiB. __device__ global (no cudaMalloc allowed).
__device__ float g_xg[268435456];

// ---- f32x2 packed-math helpers (sm_103a FFMA2) --------------------------
__device__ __forceinline__ u64 pack2(float lo, float hi) {
    u64 r; asm("mov.b64 %0, {%1, %2};" : "=l"(r) : "f"(lo), "f"(hi)); return r;
}
__device__ __forceinline__ u64 dup2(float v) {
    u64 r; asm("mov.b64 %0, {%1, %1};" : "=l"(r) : "f"(v)); return r;
}
__device__ __forceinline__ void ffma2(u64& d, u64 a, u64 b) {
    asm("fma.rn.f32x2 %0, %1, %2, %0;" : "+l"(d) : "l"(a), "l"(b));
}
__device__ __forceinline__ u64 add2(u64 a, u64 b) {
    u64 r; asm("add.rn.f32x2 %0, %1, %2;" : "=l"(r) : "l"(a), "l"(b)); return r;
}
__device__ __forceinline__ void unpack2(u64 v, float& lo, float& hi) {
    asm("mov.b64 {%0, %1}, %2;" : "=f"(lo), "=f"(hi) : "l"(v));
}

// HW tanh (sm_75+): single instruction, abs err ~1e-4, saturates correctly.
__device__ __forceinline__ float tanhapx(float x) {
    float r; asm("tanh.approx.f32 %0, %1;" : "=f"(r) : "f"(x)); return r;
}
__device__ __forceinline__ float sigapx(float x) {
    return fmaf(0.5f, tanhapx(0.5f * x), 0.5f);
}

// ---------------------------------------------------------------------------
// Kernel A: xg = x @ Wih^T + bih + bhh  (unchanged; ~95% of fp32x2 roofline)
// ---------------------------------------------------------------------------
__global__ void __launch_bounds__(256, 2)
xg_gemm(const float* __restrict__ x, const float* __restrict__ Wih,
        const float* __restrict__ bih, const float* __restrict__ bhh)
{
    extern __shared__ float sm[];
    float* As = sm;
    float* B0 = sm + 8192;
    float* B1 = B0 + 8192;

    const int tid = threadIdx.x;
    const int tx = tid & 31;
    const int ty = tid >> 5;
    const long row0 = (long)blockIdx.x * 64;
    const int g0 = blockIdx.y * 128;

    {
        const float4* x4 = (const float4*)x + row0 * 32;
        float4* As4 = (float4*)As;
#pragma unroll
        for (int i = 0; i < 8; ++i) As4[i * 256 + tid] = x4[i * 256 + tid];
    }
    {
        const float4* w4 = (const float4*)Wih + (long)g0 * 32;
#pragma unroll
        for (int i = 0; i < 16; ++i) {
            int idx = i * 256 + tid;
            int q  = idx >> 7;
            int gl = idx & 127;
            float4 w = w4[(long)gl * 32 + q];
            float* dst = (gl < 64 ? B0 : B1) + (gl & 63);
            int k = q * 4;
            dst[(k + 0) * 64] = w.x;
            dst[(k + 1) * 64] = w.y;
            dst[(k + 2) * 64] = w.z;
            dst[(k + 3) * 64] = w.w;
        }
    }
    __syncthreads();

    u64 acc0[8], acc1[8];
#pragma unroll
    for (int i = 0; i < 8; ++i) { acc0[i] = 0ull; acc1[i] = 0ull; }

    const float4* As4 = (const float4*)As;

#pragma unroll 2
    for (int k4 = 0; k4 < 32; ++k4) {
        float4 a[8];
#pragma unroll
        for (int i = 0; i < 8; ++i) a[i] = As4[(ty * 8 + i) * 32 + k4];
#pragma unroll
        for (int c = 0; c < 4; ++c) {
            int k = 4 * k4 + c;
            u64 b0 = *(const u64*)(B0 + k * 64 + 2 * tx);
            u64 b1 = *(const u64*)(B1 + k * 64 + 2 * tx);
#pragma unroll
            for (int i = 0; i < 8; ++i) {
                float av = (c == 0) ? a[i].x : (c == 1) ? a[i].y
                          : (c == 2) ? a[i].z : a[i].w;
                u64 ad = dup2(av);
                ffma2(acc0[i], ad, b0);
                ffma2(acc1[i], ad, b1);
            }
        }
    }

    int c00 = g0 + 2 * tx, c10 = g0 + 64 + 2 * tx;
    float2 bv0 = make_float2(bih[c00] + bhh[c00], bih[c00 + 1] + bhh[c00 + 1]);
    float2 bv1 = make_float2(bih[c10] + bhh[c10], bih[c10 + 1] + bhh[c10 + 1]);

#pragma unroll
    for (int i = 0; i < 8; ++i) {
        long r = row0 + ty * 8 + i;
        float lo, hi;
        unpack2(acc0[i], lo, hi);
        *(float2*)&g_xg[r * 512 + c00] = make_float2(lo + bv0.x, hi + bv0.y);
        unpack2(acc1[i], lo, hi);
        *(float2*)&g_xg[r * 512 + c10] = make_float2(lo + bv1.x, hi + bv1.y);
    }
}

// ---------------------------------------------------------------------------
// Kernel B: LSTM recurrence. 128 CTAs x 2 rows, 512 threads/CTA.
// Lane map: lane = (j&7) | (kq<<3), warp = j>>3 -> all 4 k-quarters of j in
// ONE warp. Cross-kq reduction = 2 butterfly shfl rounds; ONE barrier/step.
// Weight smem quarter-interleaved: W4s[(qq*128+j)*4+kq] -> warp loads are a
// contiguous 512B block (4 wavefronts, conflict-free).
// h smem quarter-interleaved per row: phys_f4 = qq*4 + kq (1-wf broadcasts).
// RKQ=20 k/quarter in registers (80 regs), SKQ=12 from smem.
// ---------------------------------------------------------------------------
__global__ void __launch_bounds__(512, 1)
lstm_rec(const float* __restrict__ Whh, const float* __restrict__ Wo,
         const float* __restrict__ bo, float* __restrict__ out)
{
    extern __shared__ float sm[];
    float4* W4s = (float4*)sm;               // [12][128][4] = 96 KB
    float* hbuf = sm + 48 * 128 * 4;         // [2 buf][2 row][128] swizzled

    const int th = threadIdx.x;
    const int lane = th & 31;
    const int j  = ((th >> 5) << 3) | (lane & 7);   // hidden index
    const int kq = (lane >> 3) & 3;                 // k-quarter
    const int row = kq & 1;                         // row this lane finalizes
    const int b0 = blockIdx.x * 2;

    // ---- smem weights, quarter-interleaved.
    // e = (qq*128 + jj)*4 + q ; k = 32*q + RKQ + qq
    for (int e = th; e < 48 * 128; e += 512) {
        int q  = e & 3;
        int jj = (e >> 2) & 127;
        int qq = e >> 9;
        int k = 32 * q + RKQ + qq;
        W4s[e] = make_float4(
            Whh[(0 * 128 + jj) * 128 + k], Whh[(1 * 128 + jj) * 128 + k],
            Whh[(2 * 128 + jj) * 128 + k], Whh[(3 * 128 + jj) * 128 + k]);
    }
    // ---- register weights: k in [32kq, 32kq+RKQ)
    u64 wifr[RKQ], wgor[RKQ];
#pragma unroll
    for (int r = 0; r < RKQ; ++r) {
        int k = 32 * kq + r;
        wifr[r] = pack2(Whh[(0 * 128 + j) * 128 + k], Whh[(1 * 128 + j) * 128 + k]);
        wgor[r] = pack2(Whh[(2 * 128 + j) * 128 + k], Whh[(3 * 128 + j) * 128 + k]);
    }

    hbuf[th] = 0.f;                          // zero both ping-pong buffers
    float c = 0.f;

    const float* xgp = g_xg + (long)(b0 + row) * T_SEQ * 512;
    float p0 = __ldg(xgp + j),       p1 = __ldg(xgp + 128 + j),
          p2 = __ldg(xgp + 256 + j), p3 = __ldg(xgp + 384 + j);

    __syncthreads();

    for (int step = 0; step < T_SEQ; ++step) {
        // swizzled h: buffer base + row*128 floats; f4 slot = qq*4 + kq
        const float4* hA4 = (const float4*)(hbuf + ((step & 1) << 9));        // row 0
        const float4* hB4 = (const float4*)(hbuf + ((step & 1) << 9) + 128);  // row 1
        float* hn = hbuf + (((step + 1) & 1) << 9);

        u64 aif0 = 0ull, ago0 = 0ull, aif1 = 0ull, ago1 = 0ull;

        // register k's: 5 float4 chunks (k = 32kq + 4qc + cc), logical f4 = 8kq+qc
        // -> phys f4 slot = qc*4 + kq
#pragma unroll
        for (int qc = 0; qc < RKQ / 4; ++qc) {
            float4 H0 = hA4[qc * 4 + kq], H1 = hB4[qc * 4 + kq];
#pragma unroll
            for (int cc = 0; cc < 4; ++cc) {
                int r = 4 * qc + cc;
                float hx0 = (cc == 0) ? H0.x : (cc == 1) ? H0.y : (cc == 2) ? H0.z : H0.w;
                float hx1 = (cc == 0) ? H1.x : (cc == 1) ? H1.y : (cc == 2) ? H1.z : H1.w;
                u64 d0 = dup2(hx0), d1 = dup2(hx1);
                ffma2(aif0, wifr[r], d0); ffma2(ago0, wgor[r], d0);
                ffma2(aif1, wifr[r], d1); ffma2(ago1, wgor[r], d1);
            }
        }
        // smem k's: k = 32kq + RKQ + qq, qq = 0..11. logical f4 = 8kq + 5 + (qq>>2)
        // -> phys f4 slot = (5 + qq/4)*4 + kq ; weights at W4s[(qq*128+j)*4+kq]
#pragma unroll
        for (int qs = 0; qs < SKQ / 4; ++qs) {
            float4 H0 = hA4[(RKQ / 4 + qs) * 4 + kq], H1 = hB4[(RKQ / 4 + qs) * 4 + kq];
#pragma unroll
            for (int cc = 0; cc < 4; ++cc) {
                int qq = 4 * qs + cc;
                float4 wv = W4s[(qq * 128 + j) * 4 + kq];
                u64 wif = pack2(wv.x, wv.y);
                u64 wgo = pack2(wv.z, wv.w);
                float hx0 = (cc == 0) ? H0.x : (cc == 1) ? H0.y : (cc == 2) ? H0.z : H0.w;
                float hx1 = (cc == 0) ? H1.x : (cc == 1) ? H1.y : (cc == 2) ? H1.z : H1.w;
                u64 d0 = dup2(hx0), d1 = dup2(hx1);
                ffma2(aif0, wif, d0); ffma2(ago0, wgo, d0);
                ffma2(aif1, wif, d1); ffma2(ago1, wgo, d1);
            }
        }

        // In-warp reduction over kq.
        // Round 1 (xor 8: kq0<->kq1, kq2<->kq3): partner sends MY row's partial.
        u64 aif = row ? aif1 : aif0;
        u64 ago = row ? ago1 : ago0;
        u64 oif = row ? aif0 : aif1;
        u64 ogo = row ? ago0 : ago1;
        aif = add2(aif, __shfl_xor_sync(0xFFFFFFFFu, oif, 8));
        ago = add2(ago, __shfl_xor_sync(0xFFFFFFFFu, ogo, 8));
        // Round 2 (xor 16: kq0<->kq2, kq1<->kq3): same row, other half.
        aif = add2(aif, __shfl_xor_sync(0xFFFFFFFFu, aif, 16));
        ago = add2(ago, __shfl_xor_sync(0xFFFFFFFFu, ago, 16));

        aif = add2(aif, pack2(p0, p1));
        ago = add2(ago, pack2(p2, p3));

        // prefetch next step's xg (redundant across kq/kq+2 -> L1 hits)
        {
            int ns = (step + 1 < T_SEQ) ? step + 1 : step;
            const float* qp = xgp + (long)ns * 512 + j;
            p0 = __ldg(qp); p1 = __ldg(qp + 128); p2 = __ldg(qp + 256); p3 = __ldg(qp + 384);
        }

        // all lanes finalize their row (kq and kq+2 are redundant/identical)
        float ai, af, ag, ao;
        unpack2(aif, ai, af); unpack2(ago, ag, ao);
        float iv = sigapx(ai), fv = sigapx(af), gv = tanhapx(ag), ov = sigapx(ao);
        c = fv * c + iv * gv;
        float nh = ov * tanhapx(c);
        if (kq < 2) {
            // swizzled store: logical f4 L = j>>2 = kqp*8+qqp -> phys (qqp*4+kqp)
            int L = j >> 2;
            int phys = ((L & 7) << 2) + (L >> 3);
            hn[(row << 7) + (phys << 2) + (j & 3)] = nh;
        }
        __syncthreads();                      // single barrier per step
    }

    // Output projection (final h in buffer 0 since T_SEQ is even; swizzled)
    if (th < 128) {
        int t = th;
        float acc0 = bo[t], acc1 = acc0;
        const float4* wo4 = (const float4*)(Wo + t * 128);
        const float4* h04 = (const float4*)hbuf;
        const float4* h14 = (const float4*)(hbuf + 128);
#pragma unroll
        for (int L = 0; L < 32; ++L) {
            int phys = ((L & 7) << 2) + (L >> 3);
            float4 wv = wo4[L];
            float4 a = h04[phys];
            float4 b = h14[phys];
            acc0 += wv.x * a.x + wv.y * a.y + wv.z * a.z + wv.w * a.w;
            acc1 += wv.x * b.x + wv.y * b.y + wv.z * b.z + wv.w * b.w;
        }
        out[b0 * 128 + t] = acc0;
        out[(b0 + 1) * 128 + t] = acc1;
    }
}

// ---------------------------------------------------------------------------

extern "C" void kernel_launch(void* const* d_in, const int* in_sizes, int n_in,
                              void* d_out, int out_size)
{
    const float* x   = (const float*)d_in[0];
    const float* Wih = (const float*)d_in[1];
    const float* Whh = (const float*)d_in[2];
    const float* bih = (const float*)d_in[3];
    const float* bhh = (const float*)d_in[4];
    const float* Wo  = (const float*)d_in[5];
    const float* bo  = (const float*)d_in[6];
    float* out = (float*)d_out;

    // lstm_rec smem: W4s 98304 B + hbuf 2*512*4 = 4096 B
    const int smB = 98304 + 4096;
    cudaFuncSetAttribute(xg_gemm, cudaFuncAttributeMaxDynamicSharedMemorySize, 98304);
    cudaFuncSetAttribute(lstm_rec, cudaFuncAttributeMaxDynamicSharedMemorySize, smB);

    xg_gemm<<<dim3(8192, 4), 256, 98304>>>(x, Wih, bih, bhh);
    lstm_rec<<<128, 512, smB>>>(Whh, Wo, bo, out);
}

// round 8
// speedup vs baseline: 1.1583x; 1.1583x over previous
#include <cuda_runtime.h>
#include <math.h>

#define T_SEQ 2048
#define BATCH 256
// Kernel B per k-quarter (32 k): RKQ in registers, SKQ in smem
#define RKQ 24
#define SKQ 8

typedef unsigned long long u64;

// xg scratch: [B][T][4H] fp32 = 1 GiB. __device__ global (no cudaMalloc allowed).
__device__ float g_xg[268435456];

// ---- f32x2 packed-math helpers (sm_103a FFMA2) --------------------------
__device__ __forceinline__ u64 pack2(float lo, float hi) {
    u64 r; asm("mov.b64 %0, {%1, %2};" : "=l"(r) : "f"(lo), "f"(hi)); return r;
}
__device__ __forceinline__ u64 dup2(float v) {
    u64 r; asm("mov.b64 %0, {%1, %1};" : "=l"(r) : "f"(v)); return r;
}
__device__ __forceinline__ void ffma2(u64& d, u64 a, u64 b) {
    asm("fma.rn.f32x2 %0, %1, %2, %0;" : "+l"(d) : "l"(a), "l"(b));
}
__device__ __forceinline__ u64 add2(u64 a, u64 b) {
    u64 r; asm("add.rn.f32x2 %0, %1, %2;" : "=l"(r) : "l"(a), "l"(b)); return r;
}
__device__ __forceinline__ void unpack2(u64 v, float& lo, float& hi) {
    asm("mov.b64 {%0, %1}, %2;" : "=f"(lo), "=f"(hi) : "l"(v));
}

// HW tanh (sm_75+): single instruction, abs err ~1e-4, saturates correctly.
__device__ __forceinline__ float tanhapx(float x) {
    float r; asm("tanh.approx.f32 %0, %1;" : "=f"(r) : "f"(x)); return r;
}
__device__ __forceinline__ float sigapx(float x) {
    return fmaf(0.5f, tanhapx(0.5f * x), 0.5f);
}

// ---------------------------------------------------------------------------
// Kernel A: xg = x @ Wih^T + bih + bhh  (unchanged; ~95% of fp32x2 roofline)
// ---------------------------------------------------------------------------
__global__ void __launch_bounds__(256, 2)
xg_gemm(const float* __restrict__ x, const float* __restrict__ Wih,
        const float* __restrict__ bih, const float* __restrict__ bhh)
{
    extern __shared__ float sm[];
    float* As = sm;
    float* B0 = sm + 8192;
    float* B1 = B0 + 8192;

    const int tid = threadIdx.x;
    const int tx = tid & 31;
    const int ty = tid >> 5;
    const long row0 = (long)blockIdx.x * 64;
    const int g0 = blockIdx.y * 128;

    {
        const float4* x4 = (const float4*)x + row0 * 32;
        float4* As4 = (float4*)As;
#pragma unroll
        for (int i = 0; i < 8; ++i) As4[i * 256 + tid] = x4[i * 256 + tid];
    }
    {
        const float4* w4 = (const float4*)Wih + (long)g0 * 32;
#pragma unroll
        for (int i = 0; i < 16; ++i) {
            int idx = i * 256 + tid;
            int q  = idx >> 7;
            int gl = idx & 127;
            float4 w = w4[(long)gl * 32 + q];
            float* dst = (gl < 64 ? B0 : B1) + (gl & 63);
            int k = q * 4;
            dst[(k + 0) * 64] = w.x;
            dst[(k + 1) * 64] = w.y;
            dst[(k + 2) * 64] = w.z;
            dst[(k + 3) * 64] = w.w;
        }
    }
    __syncthreads();

    u64 acc0[8], acc1[8];
#pragma unroll
    for (int i = 0; i < 8; ++i) { acc0[i] = 0ull; acc1[i] = 0ull; }

    const float4* As4 = (const float4*)As;

#pragma unroll 2
    for (int k4 = 0; k4 < 32; ++k4) {
        float4 a[8];
#pragma unroll
        for (int i = 0; i < 8; ++i) a[i] = As4[(ty * 8 + i) * 32 + k4];
#pragma unroll
        for (int c = 0; c < 4; ++c) {
            int k = 4 * k4 + c;
            u64 b0 = *(const u64*)(B0 + k * 64 + 2 * tx);
            u64 b1 = *(const u64*)(B1 + k * 64 + 2 * tx);
#pragma unroll
            for (int i = 0; i < 8; ++i) {
                float av = (c == 0) ? a[i].x : (c == 1) ? a[i].y
                          : (c == 2) ? a[i].z : a[i].w;
                u64 ad = dup2(av);
                ffma2(acc0[i], ad, b0);
                ffma2(acc1[i], ad, b1);
            }
        }
    }

    int c00 = g0 + 2 * tx, c10 = g0 + 64 + 2 * tx;
    float2 bv0 = make_float2(bih[c00] + bhh[c00], bih[c00 + 1] + bhh[c00 + 1]);
    float2 bv1 = make_float2(bih[c10] + bhh[c10], bih[c10 + 1] + bhh[c10 + 1]);

#pragma unroll
    for (int i = 0; i < 8; ++i) {
        long r = row0 + ty * 8 + i;
        float lo, hi;
        unpack2(acc0[i], lo, hi);
        *(float2*)&g_xg[r * 512 + c00] = make_float2(lo + bv0.x, hi + bv0.y);
        unpack2(acc1[i], lo, hi);
        *(float2*)&g_xg[r * 512 + c10] = make_float2(lo + bv1.x, hi + bv1.y);
    }
}

// ---------------------------------------------------------------------------
// Kernel B: LSTM recurrence, ROW-STAGGERED pipeline. 128 CTAs x 2 rows,
// 512 threads (j = th&127, kq = th>>7; R6 topology: warp = 32 consecutive j).
// Phase p: [finalize row p^1 from last phase's partials, by kq==p^1 threads]
// overlapped with [FMA for row p&1 by ALL threads], then ONE barrier.
// 2 phases = 1 LSTM step. Weights: RKQ=24 k in regs, SKQ=8 k in smem
// (loaded each phase -> crossbar 2*8*512*16/128 = 1024 cyc/step = FMA floor).
// ---------------------------------------------------------------------------
__global__ void __launch_bounds__(512, 1)
lstm_rec(const float* __restrict__ Whh, const float* __restrict__ Wo,
         const float* __restrict__ bo, float* __restrict__ out)
{
    extern __shared__ float sm[];
    float4* W4s = (float4*)sm;                   // [32][128] float4 = 64 KB
    float* hbuf = sm + 32 * 128 * 4;             // [2 rows][128] (single buf)
    ulonglong2* part = (ulonglong2*)(hbuf + 256);// [2 rows][4 kq][128]

    const int th = threadIdx.x;
    const int j  = th & 127;
    const int kq = th >> 7;                      // k-quarter 0..3
    const int b0 = blockIdx.x * 2;

    // ---- smem weights: ks = kq_w*8 + qq, k = 32*kq_w + RKQ + qq
    for (int e = th; e < 32 * 128; e += 512) {
        int ks = e >> 7, jj = e & 127;
        int kw = ks >> 3, qq = ks & 7;
        int k = 32 * kw + RKQ + qq;
        W4s[ks * 128 + jj] = make_float4(
            Whh[(0 * 128 + jj) * 128 + k], Whh[(1 * 128 + jj) * 128 + k],
            Whh[(2 * 128 + jj) * 128 + k], Whh[(3 * 128 + jj) * 128 + k]);
    }
    // ---- register weights: k in [32kq, 32kq+RKQ)  (96 regs)
    u64 wifr[RKQ], wgor[RKQ];
#pragma unroll
    for (int r = 0; r < RKQ; ++r) {
        int k = 32 * kq + r;
        wifr[r] = pack2(Whh[(0 * 128 + j) * 128 + k], Whh[(1 * 128 + j) * 128 + k]);
        wgor[r] = pack2(Whh[(2 * 128 + j) * 128 + k], Whh[(3 * 128 + j) * 128 + k]);
    }

    if (th < 256) hbuf[th] = 0.f;
    float c = 0.f;                               // cell state (kq<2 only)

    // finalizer kq<2 handles row = kq
    const float* xgp = g_xg + (long)(b0 + (kq & 1)) * T_SEQ * 512;
    float p0 = 0.f, p1 = 0.f, p2 = 0.f, p3 = 0.f;
    if (kq < 2) {
        p0 = __ldg(xgp + j);       p1 = __ldg(xgp + 128 + j);
        p2 = __ldg(xgp + 256 + j); p3 = __ldg(xgp + 384 + j);
    }

    __syncthreads();

    for (int phase = 0; phase <= 2 * T_SEQ; ++phase) {
        const int row  = phase & 1;              // row being FMA'd this phase
        const int frow = row ^ 1;                // row being finalized

        // ---- finalize frow (step (phase-1)/2) from last phase's partials
        if (kq == frow && phase > 0) {
            ulonglong2 v0 = part[(frow << 9) + (0 << 7) + j];
            ulonglong2 v1 = part[(frow << 9) + (1 << 7) + j];
            ulonglong2 v2 = part[(frow << 9) + (2 << 7) + j];
            ulonglong2 v3 = part[(frow << 9) + (3 << 7) + j];
            u64 aif = add2(add2(v0.x, v1.x), add2(v2.x, v3.x));
            u64 ago = add2(add2(v0.y, v1.y), add2(v2.y, v3.y));
            aif = add2(aif, pack2(p0, p1));
            ago = add2(ago, pack2(p2, p3));

            // prefetch xg for my next step
            int ns = ((phase - 1) >> 1) + 1;
            if (ns > T_SEQ - 1) ns = T_SEQ - 1;
            const float* qp = xgp + (long)ns * 512 + j;
            p0 = __ldg(qp); p1 = __ldg(qp + 128); p2 = __ldg(qp + 256); p3 = __ldg(qp + 384);

            float ai, af, ag, ao;
            unpack2(aif, ai, af); unpack2(ago, ag, ao);
            float iv = sigapx(ai), fv = sigapx(af), gv = tanhapx(ag), ov = sigapx(ao);
            c = fv * c + iv * gv;
            hbuf[(frow << 7) + j] = ov * tanhapx(c);
        }

        // ---- FMA for 'row' (all threads) over my 32 k's
        if (phase < 2 * T_SEQ) {
            const float4* h4 = (const float4*)(hbuf + (row << 7)) + (kq << 3);
            u64 aif = 0ull, ago = 0ull;
            // register k's: 6 float4 chunks (24 k)
#pragma unroll
            for (int qc = 0; qc < RKQ / 4; ++qc) {
                float4 H = h4[qc];
#pragma unroll
                for (int cc = 0; cc < 4; ++cc) {
                    int r = 4 * qc + cc;
                    float hx = (cc == 0) ? H.x : (cc == 1) ? H.y : (cc == 2) ? H.z : H.w;
                    u64 d = dup2(hx);
                    ffma2(aif, wifr[r], d);
                    ffma2(ago, wgor[r], d);
                }
            }
            // smem k's: 2 float4 chunks (8 k)
#pragma unroll
            for (int qs = 0; qs < SKQ / 4; ++qs) {
                float4 H = h4[RKQ / 4 + qs];
#pragma unroll
                for (int cc = 0; cc < 4; ++cc) {
                    float4 wv = W4s[((kq << 3) + 4 * qs + cc) * 128 + j];
                    float hx = (cc == 0) ? H.x : (cc == 1) ? H.y : (cc == 2) ? H.z : H.w;
                    u64 d = dup2(hx);
                    ffma2(aif, pack2(wv.x, wv.y), d);
                    ffma2(ago, pack2(wv.z, wv.w), d);
                }
            }
            part[(row << 9) + (kq << 7) + j] = make_ulonglong2(aif, ago);
        }

        __syncthreads();                         // one barrier per phase
    }

    // Output projection: out[b, o] = h_last[b,:] . Wo[o,:] + bo[o]
    if (th < 128) {
        int t = th;
        float acc0 = bo[t], acc1 = acc0;
        const float4* wo4 = (const float4*)(Wo + t * 128);
        const float4* h04 = (const float4*)hbuf;
        const float4* h14 = (const float4*)(hbuf + 128);
#pragma unroll
        for (int k4 = 0; k4 < 32; ++k4) {
            float4 wv = wo4[k4];
            float4 a = h04[k4];
            float4 b = h14[k4];
            acc0 += wv.x * a.x + wv.y * a.y + wv.z * a.z + wv.w * a.w;
            acc1 += wv.x * b.x + wv.y * b.y + wv.z * b.z + wv.w * b.w;
        }
        out[b0 * 128 + t] = acc0;
        out[(b0 + 1) * 128 + t] = acc1;
    }
}

// ---------------------------------------------------------------------------

extern "C" void kernel_launch(void* const* d_in, const int* in_sizes, int n_in,
                              void* d_out, int out_size)
{
    const float* x   = (const float*)d_in[0];
    const float* Wih = (const float*)d_in[1];
    const float* Whh = (const float*)d_in[2];
    const float* bih = (const float*)d_in[3];
    const float* bhh = (const float*)d_in[4];
    const float* Wo  = (const float*)d_in[5];
    const float* bo  = (const float*)d_in[6];
    float* out = (float*)d_out;

    // lstm_rec smem: W4s 65536 B + hbuf 1024 B + part 2*4*128*16 = 16384 B
    const int smB = 65536 + 1024 + 16384;
    cudaFuncSetAttribute(xg_gemm, cudaFuncAttributeMaxDynamicSharedMemorySize, 98304);
    cudaFuncSetAttribute(lstm_rec, cudaFuncAttributeMaxDynamicSharedMemorySize, smB);

    xg_gemm<<<dim3(8192, 4), 256, 98304>>>(x, Wih, bih, bhh);
    lstm_rec<<<128, 512, smB>>>(Whh, Wo, bo, out);
}

// round 10
// speedup vs baseline: 1.9120x; 1.6507x over previous
#include <cuda_runtime.h>
#include <cuda_bf16.h>
#include <math.h>

#define T_SEQ 2048
#define BATCH 256
// lstm_rec per k-quarter (32 k): RKQ in registers, SKQ in smem (R6 config)
#define RKQ 20
#define SKQ 12

typedef unsigned long long u64;

// xg scratch: [B][T][4H] fp32 = 1 GiB. __device__ global (no cudaMalloc allowed).
__device__ float g_xg[268435456];

// ---- f32x2 packed-math helpers (sm_103a FFMA2) --------------------------
__device__ __forceinline__ u64 pack2(float lo, float hi) {
    u64 r; asm("mov.b64 %0, {%1, %2};" : "=l"(r) : "f"(lo), "f"(hi)); return r;
}
__device__ __forceinline__ u64 dup2(float v) {
    u64 r; asm("mov.b64 %0, {%1, %1};" : "=l"(r) : "f"(v)); return r;
}
__device__ __forceinline__ void ffma2(u64& d, u64 a, u64 b) {
    asm("fma.rn.f32x2 %0, %1, %2, %0;" : "+l"(d) : "l"(a), "l"(b));
}
__device__ __forceinline__ u64 add2(u64 a, u64 b) {
    u64 r; asm("add.rn.f32x2 %0, %1, %2;" : "=l"(r) : "l"(a), "l"(b)); return r;
}
__device__ __forceinline__ void unpack2(u64 v, float& lo, float& hi) {
    asm("mov.b64 {%0, %1}, %2;" : "=f"(lo), "=f"(hi) : "l"(v));
}
__device__ __forceinline__ float tanhapx(float x) {
    float r; asm("tanh.approx.f32 %0, %1;" : "=f"(r) : "f"(x)); return r;
}
__device__ __forceinline__ float sigapx(float x) {
    return fmaf(0.5f, tanhapx(0.5f * x), 0.5f);
}

// ============================================================================
// Kernel A: xg = x @ Wih^T + bih + bhh via mma.sync bf16-3x (HMMA fallback).
// 4096 CTAs x 256 threads (8 warps). Per CTA: X tile [128 rows][128 k] ->
// bf16 hi/lo in swizzled smem (once); 8 N-chunks of 64 gates: W chunk hi/lo,
// 3 passes (hi.hi + lo.hi + hi.lo) of m16n8k16 MMAs, staged coalesced STG.
// Swizzle: 16B-chunk c of row r stored at c ^ (r&7)  (conflict-free ldmatrix).
// ============================================================================

__device__ __forceinline__ unsigned smem_u32(const void* p) {
    unsigned a;
    asm("{ .reg .u64 t; cvta.to.shared.u64 t, %1; cvt.u32.u64 %0, t; }"
        : "=r"(a) : "l"(p));
    return a;
}
__device__ __forceinline__ void ldmatrix_x4(unsigned* r, unsigned addr) {
    asm volatile("ldmatrix.sync.aligned.m8n8.x4.shared.b16 {%0,%1,%2,%3}, [%4];"
                 : "=r"(r[0]), "=r"(r[1]), "=r"(r[2]), "=r"(r[3]) : "r"(addr));
}
__device__ __forceinline__ void ldmatrix_x2(unsigned* r, unsigned addr) {
    asm volatile("ldmatrix.sync.aligned.m8n8.x2.shared.b16 {%0,%1}, [%2];"
                 : "=r"(r[0]), "=r"(r[1]) : "r"(addr));
}
__device__ __forceinline__ void mma_bf16(float* d, const unsigned* a, const unsigned* b) {
    asm volatile(
        "mma.sync.aligned.m16n8k16.row.col.f32.bf16.bf16.f32 "
        "{%0,%1,%2,%3}, {%4,%5,%6,%7}, {%8,%9}, {%0,%1,%2,%3};"
        : "+f"(d[0]), "+f"(d[1]), "+f"(d[2]), "+f"(d[3])
        : "r"(a[0]), "r"(a[1]), "r"(a[2]), "r"(a[3]), "r"(b[0]), "r"(b[1]));
}
__device__ __forceinline__ unsigned short bfbits(__nv_bfloat16 h) {
    unsigned short s; memcpy(&s, &h, 2); return s;
}
// swizzled byte offset of 16B chunk c in row r (rows of 256B = 128 bf16)
__device__ __forceinline__ unsigned sw_off(int r, int c) {
    return (unsigned)r * 256u + (unsigned)(c ^ (r & 7)) * 16u;
}

// smem layout (bytes)
#define SM_XHI 0
#define SM_XLO 32768
#define SM_WHI 65536
#define SM_WLO 81920
#define SM_STAGE 98304            // [128][68] f32 = 34816 B
#define SM_TOTAL_A 133120

__global__ void __launch_bounds__(256, 1)
xg_mma(const float* __restrict__ x, const float* __restrict__ Wih,
       const float* __restrict__ bih, const float* __restrict__ bhh)
{
    extern __shared__ char smc[];
    float* STG = (float*)(smc + SM_STAGE);
    const unsigned smem_base = smem_u32(smc);
    const unsigned XHIb = smem_base + SM_XHI, XLOb = smem_base + SM_XLO;
    const unsigned WHIb = smem_base + SM_WHI, WLOb = smem_base + SM_WLO;

    const int tid = threadIdx.x;
    const int lane = tid & 31, w = tid >> 5;
    const long row0 = (long)blockIdx.x * 128;

    // ---- Convert X tile: 128 rows x 128 k fp32 -> bf16 hi/lo, swizzled.
    {
        const float4* x4 = (const float4*)x + row0 * 32;
#pragma unroll 4
        for (int i = 0; i < 16; ++i) {
            int e = i * 256 + tid;
            int r = e >> 5, f4c = e & 31;       // k = 4*f4c
            float4 v = x4[(long)r * 32 + f4c];
            int k = 4 * f4c;
            unsigned off = sw_off(r, k >> 3) + (unsigned)(k & 7) * 2u;
            __nv_bfloat16 hx = __float2bfloat16_rn(v.x);
            __nv_bfloat16 hy = __float2bfloat16_rn(v.y);
            __nv_bfloat16 hz = __float2bfloat16_rn(v.z);
            __nv_bfloat16 hw = __float2bfloat16_rn(v.w);
            u64 hi = (u64)bfbits(hx) | ((u64)bfbits(hy) << 16)
                   | ((u64)bfbits(hz) << 32) | ((u64)bfbits(hw) << 48);
            __nv_bfloat16 lx = __float2bfloat16_rn(v.x - __bfloat162float(hx));
            __nv_bfloat16 ly = __float2bfloat16_rn(v.y - __bfloat162float(hy));
            __nv_bfloat16 lz = __float2bfloat16_rn(v.z - __bfloat162float(hz));
            __nv_bfloat16 lw = __float2bfloat16_rn(v.w - __bfloat162float(hw));
            u64 lo = (u64)bfbits(lx) | ((u64)bfbits(ly) << 16)
                   | ((u64)bfbits(lz) << 32) | ((u64)bfbits(lw) << 48);
            *(u64*)(smc + SM_XHI + off) = hi;
            *(u64*)(smc + SM_XLO + off) = lo;
        }
    }
    __syncthreads();

    // ldmatrix lane address components
    const int a_row = (w << 4) + (lane & 15);        // warp's 16-row strip
    const int a_cs  = lane >> 4;                     // 0/1 chunk select
    const int b_g   = lane & 7;                      // g-row within n8 tile
    const int b_cs  = (lane >> 3) & 1;               // 0/1 chunk select

    for (int ch = 0; ch < 8; ++ch) {
        const int g0 = ch * 64;
        // ---- Convert W chunk: 64 rows x 128 k
        {
            const float4* w4 = (const float4*)Wih + (long)g0 * 32;
#pragma unroll 4
            for (int i = 0; i < 8; ++i) {
                int e = i * 256 + tid;
                int r = e >> 5, f4c = e & 31;
                float4 v = w4[(long)r * 32 + f4c];
                int k = 4 * f4c;
                unsigned off = sw_off(r, k >> 3) + (unsigned)(k & 7) * 2u;
                __nv_bfloat16 hx = __float2bfloat16_rn(v.x);
                __nv_bfloat16 hy = __float2bfloat16_rn(v.y);
                __nv_bfloat16 hz = __float2bfloat16_rn(v.z);
                __nv_bfloat16 hw = __float2bfloat16_rn(v.w);
                u64 hi = (u64)bfbits(hx) | ((u64)bfbits(hy) << 16)
                       | ((u64)bfbits(hz) << 32) | ((u64)bfbits(hw) << 48);
                __nv_bfloat16 lx = __float2bfloat16_rn(v.x - __bfloat162float(hx));
                __nv_bfloat16 ly = __float2bfloat16_rn(v.y - __bfloat162float(hy));
                __nv_bfloat16 lz = __float2bfloat16_rn(v.z - __bfloat162float(hz));
                __nv_bfloat16 lw = __float2bfloat16_rn(v.w - __bfloat162float(hw));
                u64 lo = (u64)bfbits(lx) | ((u64)bfbits(ly) << 16)
                       | ((u64)bfbits(lz) << 32) | ((u64)bfbits(lw) << 48);
                *(u64*)(smc + SM_WHI + off) = hi;
                *(u64*)(smc + SM_WLO + off) = lo;
            }
        }
        __syncthreads();

        float acc[8][4];
#pragma unroll
        for (int nt = 0; nt < 8; ++nt)
#pragma unroll
            for (int q = 0; q < 4; ++q) acc[nt][q] = 0.f;

        // 3 precision passes: (Xhi,Whi), (Xlo,Whi), (Xhi,Wlo)
#pragma unroll
        for (int pass = 0; pass < 3; ++pass) {
            unsigned ab = (pass == 1) ? XLOb : XHIb;
            unsigned bb = (pass == 2) ? WLOb : WHIb;
#pragma unroll
            for (int ks = 0; ks < 8; ++ks) {
                unsigned afrag[4];
                ldmatrix_x4(afrag, ab + sw_off(a_row, 2 * ks + a_cs));
#pragma unroll
                for (int nt = 0; nt < 8; ++nt) {
                    unsigned bfrag[2];
                    ldmatrix_x2(bfrag, bb + sw_off(nt * 8 + b_g, 2 * ks + b_cs));
                    mma_bf16(acc[nt], afrag, bfrag);
                }
            }
        }

        // ---- Stage accumulators: thread holds rows (w*16 + lane/4, +8),
        // cols nt*8 + (lane%4)*2 + {0,1}
        {
            int r0 = (w << 4) + (lane >> 2);
            int c0 = (lane & 3) * 2;
#pragma unroll
            for (int nt = 0; nt < 8; ++nt) {
                int c = nt * 8 + c0;
                *(float2*)&STG[r0 * 68 + c]       = make_float2(acc[nt][0], acc[nt][1]);
                *(float2*)&STG[(r0 + 8) * 68 + c] = make_float2(acc[nt][2], acc[nt][3]);
            }
        }
        __syncthreads();

        // ---- Coalesced STG with bias: 8 iters x (16 rows x 64 cols)
        {
            int cseg = tid & 15;                 // 4-col group
            int C = g0 + cseg * 4;
            float4 bi = __ldg((const float4*)bih + (C >> 2));
            float4 bh = __ldg((const float4*)bhh + (C >> 2));
            float4 bias = make_float4(bi.x + bh.x, bi.y + bh.y,
                                      bi.z + bh.z, bi.w + bh.w);
#pragma unroll
            for (int it = 0; it < 8; ++it) {
                int rr = (tid >> 4) + 16 * it;
                float4 v = *(const float4*)&STG[rr * 68 + cseg * 4];
                v.x += bias.x; v.y += bias.y; v.z += bias.z; v.w += bias.w;
                *(float4*)&g_xg[(row0 + rr) * 512 + C] = v;
            }
        }
        __syncthreads();
    }
}

// ---------------------------------------------------------------------------
// Kernel B: LSTM recurrence — R6 version VERBATIM (best known).
// ---------------------------------------------------------------------------
__global__ void __launch_bounds__(512, 1)
lstm_rec(const float* __restrict__ Whh, const float* __restrict__ Wo,
         const float* __restrict__ bo, float* __restrict__ out)
{
    extern __shared__ float sm[];
    float4* W4s = (float4*)sm;               // [48][128] (wi,wf,wg,wo) = 96 KB
    float* hbuf = sm + 48 * 128 * 4;         // [2][256] ping-pong (row*128+j)
    ulonglong2* part = (ulonglong2*)(hbuf + 512);  // [2][4][128] (aif,ago)

    const int th = threadIdx.x;
    const int j  = th & 127;
    const int kq = th >> 7;
    const int b0 = blockIdx.x * 2;
    const int k0 = 32 * kq;

    for (int e = th; e < 48 * 128; e += 512) {
        int jj = e & 127, ks = e >> 7;
        int q = ks / SKQ, kk = ks % SKQ;
        int k = 32 * q + RKQ + kk;
        W4s[ks * 128 + jj] = make_float4(
            Whh[(0 * 128 + jj) * 128 + k], Whh[(1 * 128 + jj) * 128 + k],
            Whh[(2 * 128 + jj) * 128 + k], Whh[(3 * 128 + jj) * 128 + k]);
    }
    u64 wifr[RKQ], wgor[RKQ];
#pragma unroll
    for (int r = 0; r < RKQ; ++r) {
        int k = k0 + r;
        wifr[r] = pack2(Whh[(0 * 128 + j) * 128 + k], Whh[(1 * 128 + j) * 128 + k]);
        wgor[r] = pack2(Whh[(2 * 128 + j) * 128 + k], Whh[(3 * 128 + j) * 128 + k]);
    }

    hbuf[th] = 0.f;
    float c = 0.f;

    const float* xgp = g_xg + (long)(b0 + (kq & 1)) * T_SEQ * 512;
    float p0 = 0.f, p1 = 0.f, p2 = 0.f, p3 = 0.f;
    if (kq < 2) {
        p0 = __ldg(xgp + j);       p1 = __ldg(xgp + 128 + j);
        p2 = __ldg(xgp + 256 + j); p3 = __ldg(xgp + 384 + j);
    }

    __syncthreads();

    for (int step = 0; step < T_SEQ; ++step) {
        const float* hc = hbuf + ((step & 1) << 8);
        float* hn = hbuf + (((step + 1) & 1) << 8);

        const float4* hA4 = (const float4*)(hc + k0);
        const float4* hB4 = (const float4*)(hc + 128 + k0);

        u64 aif0 = 0ull, ago0 = 0ull, aif1 = 0ull, ago1 = 0ull;

#pragma unroll
        for (int q = 0; q < RKQ / 4; ++q) {
            float4 H0 = hA4[q], H1 = hB4[q];
#pragma unroll
            for (int cc = 0; cc < 4; ++cc) {
                int r = 4 * q + cc;
                float hx0 = (cc == 0) ? H0.x : (cc == 1) ? H0.y : (cc == 2) ? H0.z : H0.w;
                float hx1 = (cc == 0) ? H1.x : (cc == 1) ? H1.y : (cc == 2) ? H1.z : H1.w;
                u64 d0 = dup2(hx0), d1 = dup2(hx1);
                ffma2(aif0, wifr[r], d0); ffma2(ago0, wgor[r], d0);
                ffma2(aif1, wifr[r], d1); ffma2(ago1, wgor[r], d1);
            }
        }
#pragma unroll
        for (int q = 0; q < SKQ / 4; ++q) {
            float4 H0 = hA4[RKQ / 4 + q], H1 = hB4[RKQ / 4 + q];
            const float4* wp = W4s + (kq * SKQ + 4 * q) * 128 + j;
#pragma unroll
            for (int cc = 0; cc < 4; ++cc) {
                float4 wv = wp[cc * 128];
                u64 wif = pack2(wv.x, wv.y);
                u64 wgo = pack2(wv.z, wv.w);
                float hx0 = (cc == 0) ? H0.x : (cc == 1) ? H0.y : (cc == 2) ? H0.z : H0.w;
                float hx1 = (cc == 0) ? H1.x : (cc == 1) ? H1.y : (cc == 2) ? H1.z : H1.w;
                u64 d0 = dup2(hx0), d1 = dup2(hx1);
                ffma2(aif0, wif, d0); ffma2(ago0, wgo, d0);
                ffma2(aif1, wif, d1); ffma2(ago1, wgo, d1);
            }
        }

        if (kq == 0) {
            part[(1 << 9) + (0 << 7) + j] = make_ulonglong2(aif1, ago1);
        } else if (kq == 1) {
            part[(0 << 9) + (1 << 7) + j] = make_ulonglong2(aif0, ago0);
        } else {
            part[(0 << 9) + (kq << 7) + j] = make_ulonglong2(aif0, ago0);
            part[(1 << 9) + (kq << 7) + j] = make_ulonglong2(aif1, ago1);
        }
        __syncthreads();

        if (kq < 2) {
            u64 aif = (kq == 0) ? aif0 : aif1;
            u64 ago = (kq == 0) ? ago0 : ago1;
#pragma unroll
            for (int qq = 1; qq < 4; ++qq) {
                int src = (kq + qq) & 3;
                ulonglong2 v = part[(kq << 9) + (src << 7) + j];
                aif = add2(aif, v.x);
                ago = add2(ago, v.y);
            }
            aif = add2(aif, pack2(p0, p1));
            ago = add2(ago, pack2(p2, p3));

            int ns = (step + 1 < T_SEQ) ? step + 1 : step;
            const float* qp = xgp + (long)ns * 512 + j;
            p0 = __ldg(qp); p1 = __ldg(qp + 128); p2 = __ldg(qp + 256); p3 = __ldg(qp + 384);

            float ai, af, ag, ao;
            unpack2(aif, ai, af); unpack2(ago, ag, ao);
            float iv = sigapx(ai), fv = sigapx(af), gv = tanhapx(ag), ov = sigapx(ao);
            c = fv * c + iv * gv;
            float nh = ov * tanhapx(c);
            hn[(kq << 7) + j] = nh;
        }
        __syncthreads();
    }

    if (th < 128) {
        int t = th;
        float acc0 = bo[t], acc1 = acc0;
        const float4* wo4 = (const float4*)(Wo + t * 128);
        const float4* h04 = (const float4*)hbuf;
        const float4* h14 = (const float4*)(hbuf + 128);
#pragma unroll
        for (int k4 = 0; k4 < 32; ++k4) {
            float4 wv = wo4[k4];
            float4 a = h04[k4];
            float4 b = h14[k4];
            acc0 += wv.x * a.x + wv.y * a.y + wv.z * a.z + wv.w * a.w;
            acc1 += wv.x * b.x + wv.y * b.y + wv.z * b.z + wv.w * b.w;
        }
        out[b0 * 128 + t] = acc0;
        out[(b0 + 1) * 128 + t] = acc1;
    }
}

// ---------------------------------------------------------------------------

extern "C" void kernel_launch(void* const* d_in, const int* in_sizes, int n_in,
                              void* d_out, int out_size)
{
    const float* x   = (const float*)d_in[0];
    const float* Wih = (const float*)d_in[1];
    const float* Whh = (const float*)d_in[2];
    const float* bih = (const float*)d_in[3];
    const float* bhh = (const float*)d_in[4];
    const float* Wo  = (const float*)d_in[5];
    const float* bo  = (const float*)d_in[6];
    float* out = (float*)d_out;

    const int smB = 98304 + 2048 + 16384;   // lstm_rec (R6)
    cudaFuncSetAttribute(xg_mma, cudaFuncAttributeMaxDynamicSharedMemorySize, SM_TOTAL_A);
    cudaFuncSetAttribute(lstm_rec, cudaFuncAttributeMaxDynamicSharedMemorySize, smB);

    xg_mma<<<4096, 256, SM_TOTAL_A>>>(x, Wih, bih, bhh);
    lstm_rec<<<128, 512, smB>>>(Whh, Wo, bo, out);
}